// round 2
// baseline (speedup 1.0000x reference)
#include <cuda_runtime.h>
#include <math.h>

// Problem constants (fixed by the dataset)
constexpr int NB = 4;      // batch
constexpr int TS = 2048;   // tokens
constexpr int ED = 1024;   // embed

// Scratch (device globals; cudaMalloc is forbidden)
__device__ float g_q[(size_t)NB * TS * ED];
__device__ float g_k[(size_t)NB * TS * ED];
__device__ float g_v[(size_t)NB * TS * ED];
__device__ float g_w[(size_t)NB * TS * TS];

// ---------------------------------------------------------------------------
// Tiled SGEMM: C[M,N] = A[M,K] * op(B) (+ bias), all row-major.
//   TRANS_B = false : B is [K,N]  (ldb = N)
//   TRANS_B = true  : B is [N,K]  (ldb = K), computes A * B^T
// Block tile 128x128, K-tile 8, 256 threads, 8x8 per-thread microtile.
// All dims are multiples of 128/8 for this problem -> no bounds checks.
// ---------------------------------------------------------------------------
constexpr int TM = 128;
constexpr int TKB = 8;
constexpr int SPAD = 4;   // smem row padding (4*(128+4)=528B, 528%32=16 -> no conflict)

template <bool TRANS_B, bool HAS_BIAS>
__global__ __launch_bounds__(256, 2) void sgemm_kernel(
    const float* __restrict__ A,
    const float* __restrict__ B,
    const float* __restrict__ bias,
    float* __restrict__ C,
    int M, int N, int K,
    long strideA, long strideB, long strideC)
{
    __shared__ float As[TKB][TM + SPAD];
    __shared__ float Bs[TKB][TM + SPAD];

    const int batch = blockIdx.z;
    A += (long)batch * strideA;
    B += (long)batch * strideB;
    C += (long)batch * strideC;

    const int bm = blockIdx.y * TM;
    const int bn = blockIdx.x * TM;

    const int t  = threadIdx.x;
    const int tx = t & 15;         // 0..15
    const int ty = t >> 4;         // 0..15
    const int row0 = ty * 8;
    const int col0 = tx * 8;

    // A-tile loader: 128 rows x 8 cols, one float4 per thread (transposed store)
    const int la_r = t >> 1;          // 0..127
    const int la_s = (t & 1) * 4;     // 0 or 4

    // B-tile loader (no-trans): 8 rows x 128 cols, one float4 per thread
    const int lb_r = t >> 5;          // 0..7
    const int lb_c = (t & 31) * 4;    // 0..124

    float acc[8][8] = {};

    for (int k0 = 0; k0 < K; k0 += TKB) {
        // Load A tile (lda = K for every GEMM in this pipeline)
        {
            float4 a4 = *reinterpret_cast<const float4*>(
                A + (long)(bm + la_r) * K + (k0 + la_s));
            As[la_s + 0][la_r] = a4.x;
            As[la_s + 1][la_r] = a4.y;
            As[la_s + 2][la_r] = a4.z;
            As[la_s + 3][la_r] = a4.w;
        }
        // Load B tile
        if (TRANS_B) {
            // B is [N,K] row-major (ldb = K); need Bs[kk][n]
            float4 b4 = *reinterpret_cast<const float4*>(
                B + (long)(bn + la_r) * K + (k0 + la_s));
            Bs[la_s + 0][la_r] = b4.x;
            Bs[la_s + 1][la_r] = b4.y;
            Bs[la_s + 2][la_r] = b4.z;
            Bs[la_s + 3][la_r] = b4.w;
        } else {
            // B is [K,N] row-major (ldb = N)
            float4 b4 = *reinterpret_cast<const float4*>(
                B + (long)(k0 + lb_r) * N + (bn + lb_c));
            *reinterpret_cast<float4*>(&Bs[lb_r][lb_c]) = b4;
        }
        __syncthreads();

#pragma unroll
        for (int kk = 0; kk < TKB; kk++) {
            float4 a0 = *reinterpret_cast<const float4*>(&As[kk][row0]);
            float4 a1 = *reinterpret_cast<const float4*>(&As[kk][row0 + 4]);
            float4 b0 = *reinterpret_cast<const float4*>(&Bs[kk][col0]);
            float4 b1 = *reinterpret_cast<const float4*>(&Bs[kk][col0 + 4]);
            float ra[8] = {a0.x, a0.y, a0.z, a0.w, a1.x, a1.y, a1.z, a1.w};
            float rb[8] = {b0.x, b0.y, b0.z, b0.w, b1.x, b1.y, b1.z, b1.w};
#pragma unroll
            for (int i = 0; i < 8; i++)
#pragma unroll
                for (int j = 0; j < 8; j++)
                    acc[i][j] = fmaf(ra[i], rb[j], acc[i][j]);
        }
        __syncthreads();
    }

    // Epilogue: optional bias, vectorized stores
    float bvals[8];
    if (HAS_BIAS) {
#pragma unroll
        for (int j = 0; j < 8; j++) bvals[j] = bias[bn + col0 + j];
    }
#pragma unroll
    for (int i = 0; i < 8; i++) {
        float4 o0, o1;
        if (HAS_BIAS) {
            o0.x = acc[i][0] + bvals[0]; o0.y = acc[i][1] + bvals[1];
            o0.z = acc[i][2] + bvals[2]; o0.w = acc[i][3] + bvals[3];
            o1.x = acc[i][4] + bvals[4]; o1.y = acc[i][5] + bvals[5];
            o1.z = acc[i][6] + bvals[6]; o1.w = acc[i][7] + bvals[7];
        } else {
            o0.x = acc[i][0]; o0.y = acc[i][1]; o0.z = acc[i][2]; o0.w = acc[i][3];
            o1.x = acc[i][4]; o1.y = acc[i][5]; o1.z = acc[i][6]; o1.w = acc[i][7];
        }
        float* cp = C + (long)(bm + row0 + i) * N + (bn + col0);
        *reinterpret_cast<float4*>(cp)     = o0;
        *reinterpret_cast<float4*>(cp + 4) = o1;
    }
}

// ---------------------------------------------------------------------------
// Row softmax over rows of length TS=2048. One block (256 threads) per row.
// ---------------------------------------------------------------------------
__global__ __launch_bounds__(256) void softmax_rows_kernel(float* __restrict__ W)
{
    constexpr int PER = TS / 256;  // 8
    float* p = W + (long)blockIdx.x * TS;
    const int t = threadIdx.x;

    float v[PER];
    float mx = -INFINITY;
#pragma unroll
    for (int i = 0; i < PER; i++) {
        v[i] = p[t + i * 256];
        mx = fmaxf(mx, v[i]);
    }
    // warp reduce max
#pragma unroll
    for (int o = 16; o > 0; o >>= 1)
        mx = fmaxf(mx, __shfl_xor_sync(0xffffffffu, mx, o));

    __shared__ float smax[8];
    __shared__ float ssum[8];
    if ((t & 31) == 0) smax[t >> 5] = mx;
    __syncthreads();
    float bmx = smax[0];
#pragma unroll
    for (int i = 1; i < 8; i++) bmx = fmaxf(bmx, smax[i]);

    float sum = 0.f;
#pragma unroll
    for (int i = 0; i < PER; i++) {
        v[i] = __expf(v[i] - bmx);
        sum += v[i];
    }
#pragma unroll
    for (int o = 16; o > 0; o >>= 1)
        sum += __shfl_xor_sync(0xffffffffu, sum, o);
    if ((t & 31) == 0) ssum[t >> 5] = sum;
    __syncthreads();
    float bsum = 0.f;
#pragma unroll
    for (int i = 0; i < 8; i++) bsum += ssum[i];

    const float inv = 1.0f / bsum;
#pragma unroll
    for (int i = 0; i < PER; i++)
        p[t + i * 256] = v[i] * inv;
}

// ---------------------------------------------------------------------------
// Launch
// ---------------------------------------------------------------------------
extern "C" void kernel_launch(void* const* d_in, const int* in_sizes, int n_in,
                              void* d_out, int out_size)
{
    const float* X  = (const float*)d_in[0];
    const float* Wq = (const float*)d_in[1];
    const float* bq = (const float*)d_in[2];
    const float* Wk = (const float*)d_in[3];
    const float* bk = (const float*)d_in[4];
    const float* Wv = (const float*)d_in[5];
    const float* bv = (const float*)d_in[6];
    float* out = (float*)d_out;

    float *q, *k, *v, *w;
    cudaGetSymbolAddress((void**)&q, g_q);
    cudaGetSymbolAddress((void**)&k, g_k);
    cudaGetSymbolAddress((void**)&v, g_v);
    cudaGetSymbolAddress((void**)&w, g_w);

    const int M = NB * TS;  // 8192

    // 1) QKV projections: [8192,1024] @ [1024,1024] + bias
    {
        dim3 grid(ED / TM, M / TM, 1);
        sgemm_kernel<false, true><<<grid, 256>>>(X, Wq, bq, q, M, ED, ED, 0, 0, 0);
        sgemm_kernel<false, true><<<grid, 256>>>(X, Wk, bk, k, M, ED, ED, 0, 0, 0);
        sgemm_kernel<false, true><<<grid, 256>>>(X, Wv, bv, v, M, ED, ED, 0, 0, 0);
    }

    // 2) sim = q @ k^T per batch: [2048,1024] x [2048,1024]^T -> [2048,2048]
    {
        dim3 grid(TS / TM, TS / TM, NB);
        sgemm_kernel<true, false><<<grid, 256>>>(
            q, k, nullptr, w, TS, TS, ED,
            (long)TS * ED, (long)TS * ED, (long)TS * TS);
    }

    // 3) softmax rows
    softmax_rows_kernel<<<NB * TS, 256>>>(w);

    // 4) out = w @ v per batch: [2048,2048] x [2048,1024] -> [2048,1024]
    {
        dim3 grid(ED / TM, TS / TM, NB);
        sgemm_kernel<false, false><<<grid, 256>>>(
            w, v, nullptr, out, TS, ED, TS,
            (long)TS * TS, (long)TS * ED, (long)TS * ED);
    }
}

// round 3
// speedup vs baseline: 1.0012x; 1.0012x over previous
#include <cuda_runtime.h>
#include <math.h>

// Problem constants (fixed by the dataset)
constexpr int NB = 4;      // batch
constexpr int TS = 2048;   // tokens
constexpr int ED = 1024;   // embed

// Scratch (device globals; cudaMalloc is forbidden)
__device__ float g_q[(size_t)NB * TS * ED];
__device__ float g_k[(size_t)NB * TS * ED];
__device__ float g_v[(size_t)NB * TS * ED];
__device__ float g_w[(size_t)NB * TS * TS];

// ---------------------------------------------------------------------------
// Tiled SGEMM: C[M,N] = A[M,K] * op(B) (+ bias), all row-major.
//   TRANS_B = false : B is [K,N]  (ldb = N)
//   TRANS_B = true  : B is [N,K]  (ldb = K), computes A * B^T
// Block tile 128x128, K-tile 8, 256 threads, 8x8 per-thread microtile.
// All dims are multiples of 128/8 for this problem -> no bounds checks.
// ---------------------------------------------------------------------------
constexpr int TM = 128;
constexpr int TKB = 8;
constexpr int SPAD = 4;   // smem row padding (4*(128+4)=528B, 528%32=16 -> no conflict)

template <bool TRANS_B, bool HAS_BIAS>
__global__ __launch_bounds__(256, 2) void sgemm_kernel(
    const float* __restrict__ A,
    const float* __restrict__ B,
    const float* __restrict__ bias,
    float* __restrict__ C,
    int M, int N, int K,
    long strideA, long strideB, long strideC)
{
    __shared__ float As[TKB][TM + SPAD];
    __shared__ float Bs[TKB][TM + SPAD];

    const int batch = blockIdx.z;
    A += (long)batch * strideA;
    B += (long)batch * strideB;
    C += (long)batch * strideC;

    const int bm = blockIdx.y * TM;
    const int bn = blockIdx.x * TM;

    const int t  = threadIdx.x;
    const int tx = t & 15;         // 0..15
    const int ty = t >> 4;         // 0..15
    const int row0 = ty * 8;
    const int col0 = tx * 8;

    // A-tile loader: 128 rows x 8 cols, one float4 per thread (transposed store)
    const int la_r = t >> 1;          // 0..127
    const int la_s = (t & 1) * 4;     // 0 or 4

    // B-tile loader (no-trans): 8 rows x 128 cols, one float4 per thread
    const int lb_r = t >> 5;          // 0..7
    const int lb_c = (t & 31) * 4;    // 0..124

    float acc[8][8] = {};

    for (int k0 = 0; k0 < K; k0 += TKB) {
        // Load A tile (lda = K for every GEMM in this pipeline)
        {
            float4 a4 = *reinterpret_cast<const float4*>(
                A + (long)(bm + la_r) * K + (k0 + la_s));
            As[la_s + 0][la_r] = a4.x;
            As[la_s + 1][la_r] = a4.y;
            As[la_s + 2][la_r] = a4.z;
            As[la_s + 3][la_r] = a4.w;
        }
        // Load B tile
        if (TRANS_B) {
            // B is [N,K] row-major (ldb = K); need Bs[kk][n]
            float4 b4 = *reinterpret_cast<const float4*>(
                B + (long)(bn + la_r) * K + (k0 + la_s));
            Bs[la_s + 0][la_r] = b4.x;
            Bs[la_s + 1][la_r] = b4.y;
            Bs[la_s + 2][la_r] = b4.z;
            Bs[la_s + 3][la_r] = b4.w;
        } else {
            // B is [K,N] row-major (ldb = N)
            float4 b4 = *reinterpret_cast<const float4*>(
                B + (long)(k0 + lb_r) * N + (bn + lb_c));
            *reinterpret_cast<float4*>(&Bs[lb_r][lb_c]) = b4;
        }
        __syncthreads();

#pragma unroll
        for (int kk = 0; kk < TKB; kk++) {
            float4 a0 = *reinterpret_cast<const float4*>(&As[kk][row0]);
            float4 a1 = *reinterpret_cast<const float4*>(&As[kk][row0 + 4]);
            float4 b0 = *reinterpret_cast<const float4*>(&Bs[kk][col0]);
            float4 b1 = *reinterpret_cast<const float4*>(&Bs[kk][col0 + 4]);
            float ra[8] = {a0.x, a0.y, a0.z, a0.w, a1.x, a1.y, a1.z, a1.w};
            float rb[8] = {b0.x, b0.y, b0.z, b0.w, b1.x, b1.y, b1.z, b1.w};
#pragma unroll
            for (int i = 0; i < 8; i++)
#pragma unroll
                for (int j = 0; j < 8; j++)
                    acc[i][j] = fmaf(ra[i], rb[j], acc[i][j]);
        }
        __syncthreads();
    }

    // Epilogue: optional bias, vectorized stores
    float bvals[8];
    if (HAS_BIAS) {
#pragma unroll
        for (int j = 0; j < 8; j++) bvals[j] = bias[bn + col0 + j];
    }
#pragma unroll
    for (int i = 0; i < 8; i++) {
        float4 o0, o1;
        if (HAS_BIAS) {
            o0.x = acc[i][0] + bvals[0]; o0.y = acc[i][1] + bvals[1];
            o0.z = acc[i][2] + bvals[2]; o0.w = acc[i][3] + bvals[3];
            o1.x = acc[i][4] + bvals[4]; o1.y = acc[i][5] + bvals[5];
            o1.z = acc[i][6] + bvals[6]; o1.w = acc[i][7] + bvals[7];
        } else {
            o0.x = acc[i][0]; o0.y = acc[i][1]; o0.z = acc[i][2]; o0.w = acc[i][3];
            o1.x = acc[i][4]; o1.y = acc[i][5]; o1.z = acc[i][6]; o1.w = acc[i][7];
        }
        float* cp = C + (long)(bm + row0 + i) * N + (bn + col0);
        *reinterpret_cast<float4*>(cp)     = o0;
        *reinterpret_cast<float4*>(cp + 4) = o1;
    }
}

// ---------------------------------------------------------------------------
// Row softmax over rows of length TS=2048. One block (256 threads) per row.
// ---------------------------------------------------------------------------
__global__ __launch_bounds__(256) void softmax_rows_kernel(float* __restrict__ W)
{
    constexpr int PER = TS / 256;  // 8
    float* p = W + (long)blockIdx.x * TS;
    const int t = threadIdx.x;

    float v[PER];
    float mx = -INFINITY;
#pragma unroll
    for (int i = 0; i < PER; i++) {
        v[i] = p[t + i * 256];
        mx = fmaxf(mx, v[i]);
    }
    // warp reduce max
#pragma unroll
    for (int o = 16; o > 0; o >>= 1)
        mx = fmaxf(mx, __shfl_xor_sync(0xffffffffu, mx, o));

    __shared__ float smax[8];
    __shared__ float ssum[8];
    if ((t & 31) == 0) smax[t >> 5] = mx;
    __syncthreads();
    float bmx = smax[0];
#pragma unroll
    for (int i = 1; i < 8; i++) bmx = fmaxf(bmx, smax[i]);

    float sum = 0.f;
#pragma unroll
    for (int i = 0; i < PER; i++) {
        v[i] = __expf(v[i] - bmx);
        sum += v[i];
    }
#pragma unroll
    for (int o = 16; o > 0; o >>= 1)
        sum += __shfl_xor_sync(0xffffffffu, sum, o);
    if ((t & 31) == 0) ssum[t >> 5] = sum;
    __syncthreads();
    float bsum = 0.f;
#pragma unroll
    for (int i = 0; i < 8; i++) bsum += ssum[i];

    const float inv = 1.0f / bsum;
#pragma unroll
    for (int i = 0; i < PER; i++)
        p[t + i * 256] = v[i] * inv;
}

// ---------------------------------------------------------------------------
// Launch
// ---------------------------------------------------------------------------
extern "C" void kernel_launch(void* const* d_in, const int* in_sizes, int n_in,
                              void* d_out, int out_size)
{
    const float* X  = (const float*)d_in[0];
    const float* Wq = (const float*)d_in[1];
    const float* bq = (const float*)d_in[2];
    const float* Wk = (const float*)d_in[3];
    const float* bk = (const float*)d_in[4];
    const float* Wv = (const float*)d_in[5];
    const float* bv = (const float*)d_in[6];
    float* out = (float*)d_out;

    float *q, *k, *v, *w;
    cudaGetSymbolAddress((void**)&q, g_q);
    cudaGetSymbolAddress((void**)&k, g_k);
    cudaGetSymbolAddress((void**)&v, g_v);
    cudaGetSymbolAddress((void**)&w, g_w);

    const int M = NB * TS;  // 8192

    // 1) QKV projections: [8192,1024] @ [1024,1024] + bias
    {
        dim3 grid(ED / TM, M / TM, 1);
        sgemm_kernel<false, true><<<grid, 256>>>(X, Wq, bq, q, M, ED, ED, 0, 0, 0);
        sgemm_kernel<false, true><<<grid, 256>>>(X, Wk, bk, k, M, ED, ED, 0, 0, 0);
        sgemm_kernel<false, true><<<grid, 256>>>(X, Wv, bv, v, M, ED, ED, 0, 0, 0);
    }

    // 2) sim = q @ k^T per batch: [2048,1024] x [2048,1024]^T -> [2048,2048]
    {
        dim3 grid(TS / TM, TS / TM, NB);
        sgemm_kernel<true, false><<<grid, 256>>>(
            q, k, nullptr, w, TS, TS, ED,
            (long)TS * ED, (long)TS * ED, (long)TS * TS);
    }

    // 3) softmax rows
    softmax_rows_kernel<<<NB * TS, 256>>>(w);

    // 4) out = w @ v per batch: [2048,2048] x [2048,1024] -> [2048,1024]
    {
        dim3 grid(ED / TM, TS / TM, NB);
        sgemm_kernel<false, false><<<grid, 256>>>(
            w, v, nullptr, out, TS, ED, TS,
            (long)TS * TS, (long)TS * ED, (long)TS * ED);
    }
}

// round 5
// speedup vs baseline: 2.7822x; 2.7790x over previous
#include <cuda_runtime.h>
#include <cuda_bf16.h>
#include <stdint.h>
#include <math.h>

using bf16 = __nv_bfloat16;

constexpr int NB = 4, TS = 2048, ED = 1024;

// GEMM tiling
constexpr int BM = 128, BN = 128, BKT = 32;      // block tile (BKT in bf16 elems)
constexpr int LDS_ELEM = 40;                      // smem row stride in bf16 (80 B)
constexpr int TILE_B = 128 * LDS_ELEM * 2;        // 10240 bytes per operand tile
constexpr int STAGE_B = 4 * TILE_B;               // Ah, Al, Bh, Bl
constexpr int SMEM_TOTAL = 2 * STAGE_B;           // 81920

#define NE (8192u * 1024u)
__device__ __align__(256) bf16 g_Xh[NE], g_Xl[NE];
__device__ __align__(256) bf16 g_Wth[3u * 1024 * 1024], g_Wtl[3u * 1024 * 1024];
__device__ __align__(256) bf16 g_Ph[3u * NE], g_Pl[3u * NE];   // Q,K,V hi/lo
__device__ __align__(256) bf16 g_VTh[NE], g_VTl[NE];
__device__ __align__(256) float g_S[(size_t)NB * TS * TS];
__device__ __align__(256) bf16 g_Sh[(size_t)NB * TS * TS], g_Sl[(size_t)NB * TS * TS];

// ---------------- helpers ----------------
__device__ __forceinline__ uint32_t smem_u32(const void* p) {
    uint32_t a;
    asm("{ .reg .u64 t; cvta.to.shared.u64 t, %1; cvt.u32.u64 %0, t; }" : "=r"(a) : "l"(p));
    return a;
}
__device__ __forceinline__ void cp16(uint32_t dst, const void* src) {
    asm volatile("cp.async.cg.shared.global [%0], [%1], 16;" :: "r"(dst), "l"(src));
}
#define CP_COMMIT() asm volatile("cp.async.commit_group;" ::: "memory")
#define CP_WAIT(n)  asm volatile("cp.async.wait_group %0;" :: "n"(n) : "memory")

__device__ __forceinline__ void ldm4(uint32_t& r0, uint32_t& r1, uint32_t& r2, uint32_t& r3, uint32_t a) {
    asm volatile("ldmatrix.sync.aligned.m8n8.x4.shared.b16 {%0,%1,%2,%3}, [%4];"
                 : "=r"(r0), "=r"(r1), "=r"(r2), "=r"(r3) : "r"(a));
}
__device__ __forceinline__ void mma16816(float* d, const uint32_t* a, const uint32_t* b) {
    asm volatile(
        "mma.sync.aligned.m16n8k16.row.col.f32.bf16.bf16.f32 "
        "{%0,%1,%2,%3}, {%4,%5,%6,%7}, {%8,%9}, {%0,%1,%2,%3};"
        : "+f"(d[0]), "+f"(d[1]), "+f"(d[2]), "+f"(d[3])
        : "r"(a[0]), "r"(a[1]), "r"(a[2]), "r"(a[3]), "r"(b[0]), "r"(b[1]));
}
__device__ __forceinline__ void split2(float x, bf16& h, bf16& l) {
    h = __float2bfloat16(x);
    l = __float2bfloat16(x - __bfloat162float(h));
}
__device__ __forceinline__ uint32_t pk(bf16 a, bf16 b) {
    __nv_bfloat162 t = __halves2bfloat162(a, b);
    return *reinterpret_cast<uint32_t*>(&t);
}

// ---------------------------------------------------------------------------
// mma.sync GEMM: C[M,N] = (Ah+Al)[M,K] * (Bh+Bl)[N,K]^T, 3-product bf16 split.
// MODE 0: fp32 C.  MODE 1: + bias(z) then bf16 hi/lo C.
// 256 threads = 8 warps, warp grid 2(m) x 4(n), warp tile 64x32.
// ---------------------------------------------------------------------------
template <int MODE>
__global__ __launch_bounds__(256) void tc_gemm(
    const bf16* __restrict__ Ah, const bf16* __restrict__ Al,
    const bf16* __restrict__ Bh, const bf16* __restrict__ Bl,
    const float* __restrict__ b0, const float* __restrict__ b1, const float* __restrict__ b2,
    float* __restrict__ Cf, bf16* __restrict__ Ch, bf16* __restrict__ Cl,
    int Kd, int Nd, long sA, long sB, long sC)
{
    extern __shared__ __align__(1024) char smem[];
    const uint32_t sb = smem_u32(smem);
    const int tid = threadIdx.x, wid = tid >> 5, lane = tid & 31;
    const int zb = blockIdx.z;
    const size_t bm = (size_t)blockIdx.y * BM;
    const size_t bn = (size_t)blockIdx.x * BN;

    Ah += (size_t)zb * sA;  Al += (size_t)zb * sA;
    Bh += (size_t)zb * sB;  Bl += (size_t)zb * sB;

    const int KT = Kd / BKT;

    // loader: per tile 512 x 16B segs; this thread does f = tid, tid+256
    const int r0g = tid >> 2,        s0g = tid & 3;          // f = tid
    const int r1g = (tid + 256) >> 2, s1g = tid & 3;         // f = tid+256

    auto prefetch = [&](int kt) {
        const uint32_t stg = sb + (kt & 1) * STAGE_B;
        const size_t k0 = (size_t)kt * BKT;
        const bf16* srcA0h = Ah + (bm + r0g) * Kd + k0 + s0g * 8;
        const bf16* srcA1h = Ah + (bm + r1g) * Kd + k0 + s1g * 8;
        const bf16* srcA0l = Al + (bm + r0g) * Kd + k0 + s0g * 8;
        const bf16* srcA1l = Al + (bm + r1g) * Kd + k0 + s1g * 8;
        const bf16* srcB0h = Bh + (bn + r0g) * Kd + k0 + s0g * 8;
        const bf16* srcB1h = Bh + (bn + r1g) * Kd + k0 + s1g * 8;
        const bf16* srcB0l = Bl + (bn + r0g) * Kd + k0 + s0g * 8;
        const bf16* srcB1l = Bl + (bn + r1g) * Kd + k0 + s1g * 8;
        const uint32_t d0 = r0g * 80 + s0g * 16;
        const uint32_t d1 = r1g * 80 + s1g * 16;
        cp16(stg + 0 * TILE_B + d0, srcA0h);  cp16(stg + 0 * TILE_B + d1, srcA1h);
        cp16(stg + 1 * TILE_B + d0, srcA0l);  cp16(stg + 1 * TILE_B + d1, srcA1l);
        cp16(stg + 2 * TILE_B + d0, srcB0h);  cp16(stg + 2 * TILE_B + d1, srcB1h);
        cp16(stg + 3 * TILE_B + d0, srcB0l);  cp16(stg + 3 * TILE_B + d1, srcB1l);
    };

    float acc[4][4][4] = {};

    const int wm = wid >> 2, wn = wid & 3;
    // ldmatrix lane addressing
    const int a_row = wm * 64 + (lane & 15);          // + i*16
    const int a_col = ((lane >> 4) & 1) * 8;          // + ks*16
    const int b_row = wn * 32 + ((lane >> 4) & 1) * 8 + (lane & 7);  // + j*16
    const int b_col = ((lane >> 3) & 1) * 8;          // + ks*16

    prefetch(0);
    CP_COMMIT();

    for (int kt = 0; kt < KT; ++kt) {
        if (kt + 1 < KT) {
            prefetch(kt + 1);
            CP_COMMIT();
            CP_WAIT(1);
        } else {
            CP_WAIT(0);
        }
        __syncthreads();

        const uint32_t stg = sb + (kt & 1) * STAGE_B;
        const uint32_t tAh = stg, tAl = stg + TILE_B, tBh = stg + 2 * TILE_B, tBl = stg + 3 * TILE_B;

#pragma unroll
        for (int ks = 0; ks < 2; ++ks) {
            uint32_t ah[4][4], al[4][4], bh[4][2], bl[4][2];
            const uint32_t aoff = (uint32_t)(a_row * 80 + (a_col + ks * 16) * 2);
            const uint32_t boff = (uint32_t)(b_row * 80 + (b_col + ks * 16) * 2);
#pragma unroll
            for (int i = 0; i < 4; i++) {
                ldm4(ah[i][0], ah[i][1], ah[i][2], ah[i][3], tAh + aoff + i * 16 * 80);
                ldm4(al[i][0], al[i][1], al[i][2], al[i][3], tAl + aoff + i * 16 * 80);
            }
#pragma unroll
            for (int j = 0; j < 2; j++) {
                uint32_t q0, q1, q2, q3;
                ldm4(q0, q1, q2, q3, tBh + boff + j * 16 * 80);
                bh[2 * j][0] = q0; bh[2 * j][1] = q1; bh[2 * j + 1][0] = q2; bh[2 * j + 1][1] = q3;
                ldm4(q0, q1, q2, q3, tBl + boff + j * 16 * 80);
                bl[2 * j][0] = q0; bl[2 * j][1] = q1; bl[2 * j + 1][0] = q2; bl[2 * j + 1][1] = q3;
            }
#pragma unroll
            for (int i = 0; i < 4; i++)
#pragma unroll
                for (int j = 0; j < 4; j++) {
                    mma16816(acc[i][j], ah[i], bh[j]);
                    mma16816(acc[i][j], ah[i], bl[j]);
                    mma16816(acc[i][j], al[i], bh[j]);
                }
        }
        __syncthreads();
    }

    // -------- epilogue --------
    const int lr = lane >> 2, lc = (lane & 3) * 2;
    const float* bias = nullptr;
    if (MODE == 1) bias = (zb == 0) ? b0 : ((zb == 1) ? b1 : b2);

#pragma unroll
    for (int i = 0; i < 4; i++) {
#pragma unroll
        for (int j = 0; j < 4; j++) {
            const size_t row0 = bm + wm * 64 + i * 16 + lr;
            const size_t col  = bn + wn * 32 + j * 8 + lc;
            if (MODE == 0) {
                float* p0 = Cf + (size_t)zb * sC + row0 * Nd + col;
                float* p1 = p0 + 8 * Nd;
                *(float2*)p0 = make_float2(acc[i][j][0], acc[i][j][1]);
                *(float2*)p1 = make_float2(acc[i][j][2], acc[i][j][3]);
            } else {
                const float bb0 = bias[col], bb1 = bias[col + 1];
                bf16 h0, l0, h1, l1;
                split2(acc[i][j][0] + bb0, h0, l0);
                split2(acc[i][j][1] + bb1, h1, l1);
                *(uint32_t*)(Ch + (size_t)zb * sC + row0 * Nd + col) = pk(h0, h1);
                *(uint32_t*)(Cl + (size_t)zb * sC + row0 * Nd + col) = pk(l0, l1);
                split2(acc[i][j][2] + bb0, h0, l0);
                split2(acc[i][j][3] + bb1, h1, l1);
                *(uint32_t*)(Ch + (size_t)zb * sC + (row0 + 8) * Nd + col) = pk(h0, h1);
                *(uint32_t*)(Cl + (size_t)zb * sC + (row0 + 8) * Nd + col) = pk(l0, l1);
            }
        }
    }
}

// ---------------- prepass kernels ----------------
__global__ void split_kernel(const float* __restrict__ in, bf16* __restrict__ oh,
                             bf16* __restrict__ ol, int n4)
{
    int i = blockIdx.x * blockDim.x + threadIdx.x;
    if (i >= n4) return;
    float4 v = ((const float4*)in)[i];
    bf16 h0, l0, h1, l1, h2, l2, h3, l3;
    split2(v.x, h0, l0); split2(v.y, h1, l1);
    split2(v.z, h2, l2); split2(v.w, h3, l3);
    ((uint2*)oh)[i] = make_uint2(pk(h0, h1), pk(h2, h3));
    ((uint2*)ol)[i] = make_uint2(pk(l0, l1), pk(l2, l3));
}

__global__ void wtrans_kernel(const float* __restrict__ Wq, const float* __restrict__ Wk,
                              const float* __restrict__ Wv)
{
    __shared__ float t[32][33];
    const float* in = (blockIdx.z == 0) ? Wq : ((blockIdx.z == 1) ? Wk : Wv);
    const size_t ob = (size_t)blockIdx.z * 1024 * 1024;
    const int bx = blockIdx.x * 32, by = blockIdx.y * 32;
    const int tx = threadIdx.x, ty = threadIdx.y;     // 32 x 8
#pragma unroll
    for (int r = 0; r < 32; r += 8)
        t[ty + r][tx] = in[(size_t)(by + ty + r) * 1024 + bx + tx];
    __syncthreads();
#pragma unroll
    for (int r = 0; r < 32; r += 8) {
        float v = t[tx][ty + r];
        size_t o = ob + (size_t)(bx + ty + r) * 1024 + by + tx;
        bf16 h, l; split2(v, h, l);
        g_Wth[o] = h; g_Wtl[o] = l;
    }
}

__global__ void vtrans_kernel()
{
    __shared__ bf16 th[32][36], tl[32][36];
    const size_t ib = (size_t)blockIdx.z * TS * ED;
    const int be = blockIdx.x * 32, bt = blockIdx.y * 32;
    const int tx = threadIdx.x, ty = threadIdx.y;     // tx<8, ty<32
    const bf16* Vh = g_Ph + 2u * NE;
    const bf16* Vl = g_Pl + 2u * NE;
    {
        size_t src = ib + (size_t)(bt + ty) * ED + be + tx * 4;
        *(uint2*)&th[ty][tx * 4] = *(const uint2*)(Vh + src);
        *(uint2*)&tl[ty][tx * 4] = *(const uint2*)(Vl + src);
    }
    __syncthreads();
    {
        bf16 oh[4], ol[4];
#pragma unroll
        for (int i = 0; i < 4; i++) { oh[i] = th[tx * 4 + i][ty]; ol[i] = tl[tx * 4 + i][ty]; }
        size_t dst = (size_t)blockIdx.z * ED * TS + (size_t)(be + ty) * TS + bt + tx * 4;
        *(uint2*)(g_VTh + dst) = *(uint2*)oh;
        *(uint2*)(g_VTl + dst) = *(uint2*)ol;
    }
}

__global__ __launch_bounds__(256) void softmax_kernel()
{
    const size_t row = blockIdx.x;
    const float4* p4 = (const float4*)(g_S + row * TS);
    const int t = threadIdx.x;
    float v[8];
    {
        float4 a = p4[2 * t], b = p4[2 * t + 1];
        v[0] = a.x; v[1] = a.y; v[2] = a.z; v[3] = a.w;
        v[4] = b.x; v[5] = b.y; v[6] = b.z; v[7] = b.w;
    }
    float mx = v[0];
#pragma unroll
    for (int i = 1; i < 8; i++) mx = fmaxf(mx, v[i]);
#pragma unroll
    for (int o = 16; o > 0; o >>= 1) mx = fmaxf(mx, __shfl_xor_sync(0xffffffffu, mx, o));
    __shared__ float smax[8], ssum[8];
    if ((t & 31) == 0) smax[t >> 5] = mx;
    __syncthreads();
    float bmx = smax[0];
#pragma unroll
    for (int i = 1; i < 8; i++) bmx = fmaxf(bmx, smax[i]);
    float sum = 0.f;
#pragma unroll
    for (int i = 0; i < 8; i++) { v[i] = __expf(v[i] - bmx); sum += v[i]; }
#pragma unroll
    for (int o = 16; o > 0; o >>= 1) sum += __shfl_xor_sync(0xffffffffu, sum, o);
    if ((t & 31) == 0) ssum[t >> 5] = sum;
    __syncthreads();
    float bsum = 0.f;
#pragma unroll
    for (int i = 0; i < 8; i++) bsum += ssum[i];
    const float inv = 1.0f / bsum;
    bf16 h[8], l[8];
#pragma unroll
    for (int i = 0; i < 8; i++) split2(v[i] * inv, h[i], l[i]);
    ((uint4*)(g_Sh + row * TS))[t] = make_uint4(pk(h[0], h[1]), pk(h[2], h[3]), pk(h[4], h[5]), pk(h[6], h[7]));
    ((uint4*)(g_Sl + row * TS))[t] = make_uint4(pk(l[0], l[1]), pk(l[2], l[3]), pk(l[4], l[5]), pk(l[6], l[7]));
}

// ---------------- launch ----------------
extern "C" void kernel_launch(void* const* d_in, const int* in_sizes, int n_in,
                              void* d_out, int out_size)
{
    const float* X  = (const float*)d_in[0];
    const float* Wq = (const float*)d_in[1];
    const float* bq = (const float*)d_in[2];
    const float* Wk = (const float*)d_in[3];
    const float* bk = (const float*)d_in[4];
    const float* Wv = (const float*)d_in[5];
    const float* bv = (const float*)d_in[6];
    float* out = (float*)d_out;

    cudaFuncSetAttribute(tc_gemm<0>, cudaFuncAttributeMaxDynamicSharedMemorySize, SMEM_TOTAL);
    cudaFuncSetAttribute(tc_gemm<1>, cudaFuncAttributeMaxDynamicSharedMemorySize, SMEM_TOTAL);

    bf16 *Xh, *Xl, *Wth, *Wtl, *Ph, *Pl, *VTh, *VTl, *Sh, *Sl;
    float* S;
    cudaGetSymbolAddress((void**)&Xh, g_Xh);   cudaGetSymbolAddress((void**)&Xl, g_Xl);
    cudaGetSymbolAddress((void**)&Wth, g_Wth); cudaGetSymbolAddress((void**)&Wtl, g_Wtl);
    cudaGetSymbolAddress((void**)&Ph, g_Ph);   cudaGetSymbolAddress((void**)&Pl, g_Pl);
    cudaGetSymbolAddress((void**)&VTh, g_VTh); cudaGetSymbolAddress((void**)&VTl, g_VTl);
    cudaGetSymbolAddress((void**)&S, g_S);
    cudaGetSymbolAddress((void**)&Sh, g_Sh);   cudaGetSymbolAddress((void**)&Sl, g_Sl);

    // 1) split X into bf16 hi/lo
    split_kernel<<<(8192 * 1024 / 4 + 255) / 256, 256>>>(X, Xh, Xl, 8192 * 1024 / 4);
    // 2) transpose + split weights
    wtrans_kernel<<<dim3(32, 32, 3), dim3(32, 8)>>>(Wq, Wk, Wv);
    // 3) QKV projections -> P hi/lo  (M=8192, N=1024, K=1024; z selects q/k/v)
    tc_gemm<1><<<dim3(ED / BN, 8192 / BM, 3), 256, SMEM_TOTAL>>>(
        Xh, Xl, Wth, Wtl, bq, bk, bv, nullptr, Ph, Pl,
        ED, ED, 0, 1024L * 1024L, (long)NE);
    // 4) transpose V -> VT hi/lo
    vtrans_kernel<<<dim3(ED / 32, TS / 32, NB), dim3(8, 32)>>>();
    // 5) sim = Q K^T (fp32)  (M=2048, N=2048, K=1024 per batch)
    tc_gemm<0><<<dim3(TS / BN, TS / BM, NB), 256, SMEM_TOTAL>>>(
        Ph, Pl, Ph + NE, Pl + NE, nullptr, nullptr, nullptr, S, nullptr, nullptr,
        ED, TS, (long)TS * ED, (long)TS * ED, (long)TS * TS);
    // 6) softmax -> S hi/lo
    softmax_kernel<<<NB * TS, 256>>>();
    // 7) out = W V  (M=2048, N=1024, K=2048 per batch; B = VT)
    tc_gemm<0><<<dim3(ED / BN, TS / BM, NB), 256, SMEM_TOTAL>>>(
        Sh, Sl, VTh, VTl, nullptr, nullptr, nullptr, out, nullptr, nullptr,
        TS, ED, (long)TS * TS, (long)ED * TS, (long)TS * ED);
}